// round 14
// baseline (speedup 1.0000x reference)
#include <cuda_runtime.h>
#include <math.h>

// Problem constants: B=2, L=1024, H=8, E=64, n_top=35 (5*ceil(ln 1024))
#define B_  2
#define L_  1024
#define H_  8
#define E_  64
#define BH_ 16
#define NT_ 35      // top-k per half
#define NS_ 70      // total selected columns
#define SCALE_ 0.125f

// packed f32x2 helpers (sm_100+): ptxas never auto-fuses these
#define FMA2(out, a, b, c) \
    asm("fma.rn.f32x2 %0, %1, %2, %3;" : "=l"(out) : "l"(a), "l"(b), "l"(c))
#define ADD2(out, a, b) \
    asm("add.rn.f32x2 %0, %1, %2;" : "=l"(out) : "l"(a), "l"(b))
#define PACK2(out, lo, hi) \
    asm("mov.b64 %0, {%1, %2};" : "=l"(out) : "f"(lo), "f"(hi))
#define UNPACK2(lo, hi, in) \
    asm("mov.b64 {%0, %1}, %2;" : "=f"(lo), "=f"(hi) : "l"(in))

// -------- static scratch (no allocations allowed) --------
// Invariant: g_amp2_t and g_usel are ZERO at kernel_launch entry (zero-init at
// module load; topk_kernel re-establishes the invariant every run).
__device__ float g_amp2_t[BH_ * L_];            // corr amplitudes^2 (atomic accum)
__device__ float g_amp2_tf[BH_ * L_];           // tf-query norms^2 (overwritten)
__device__ int   g_selidx[BH_ * NS_];           // [0..34]=idx_t, [35..69]=idx_tf
__device__ float g_usel[BH_ * 71 * E_];         // row 70 = bias row bv

__device__ __forceinline__ float2 cmulf(float2 a, float2 b) {
    return make_float2(a.x * b.x - a.y * b.y, a.x * b.y + a.y * b.x);
}

// Kernel 1: blocks [0,1024): FFT circular correlation per channel (b,h,e),
// atomic-accumulating ac^2 into g_amp2_t. blocks [1024,1040): tf-query row
// norms^2 per (b,h), direct store into g_amp2_tf.
__global__ void __launch_bounds__(256) corr_tf_kernel(const float* __restrict__ q,
                                                      const float* __restrict__ k,
                                                      const float* __restrict__ tfq) {
    __shared__ float2 bufA[L_];
    __shared__ float2 bufB[L_];
    int tid = threadIdx.x;

    if (blockIdx.x >= 1024) {
        // ---- tf-norm role ----
        int bh = blockIdx.x - 1024;
        int b = bh >> 3, h = bh & 7;
        #pragma unroll
        for (int jj = 0; jj < 4; jj++) {
            int l = tid + jj * 256;
            const float4* p = (const float4*)(tfq + (((size_t)(b * L_ + l) * H_ + h) * E_));
            float s = 0.f;
            #pragma unroll
            for (int j = 0; j < 16; j++) {
                float4 x = p[j];
                s += x.x * x.x + x.y * x.y + x.z * x.z + x.w * x.w;
            }
            g_amp2_tf[bh * L_ + l] = s;
        }
        return;
    }

    // ---- corr role ----
    int ch = blockIdx.x;            // b*512 + h*64 + e
    int e  = ch & 63;
    int bh = ch >> 6;
    int h  = bh & 7;
    int b  = bh >> 3;

    size_t base = (size_t)b * (L_ * H_ * E_) + (size_t)h * E_ + e;
    #pragma unroll
    for (int jj = 0; jj < 4; jj++) {
        int l = tid + jj * 256;
        bufA[l] = make_float2(q[base + (size_t)l * (H_ * E_)],
                              k[base + (size_t)l * (H_ * E_)]);
    }
    __syncthreads();

    float2* X = bufA;
    float2* Y = bufB;

    #pragma unroll
    for (int stage = 0; stage < 5; stage++) {
        int s2 = 2 * stage;
        int Ns = 1 << s2;
        int j = tid;
        float2 v0 = X[j];
        float2 v1 = X[j + 256];
        float2 v2 = X[j + 512];
        float2 v3 = X[j + 768];
        int jm = j & (Ns - 1);
        float ang = -6.28318530717958647692f * (float)jm / (float)(4 * Ns);
        float sn, cs;
        __sincosf(ang, &sn, &cs);
        float2 w1 = make_float2(cs, sn);
        float2 w2 = cmulf(w1, w1);
        float2 w3 = cmulf(w2, w1);
        v1 = cmulf(v1, w1);
        v2 = cmulf(v2, w2);
        v3 = cmulf(v3, w3);
        float2 t0 = make_float2(v0.x + v2.x, v0.y + v2.y);
        float2 t1 = make_float2(v0.x - v2.x, v0.y - v2.y);
        float2 t2 = make_float2(v1.x + v3.x, v1.y + v3.y);
        float2 t3 = make_float2(v1.x - v3.x, v1.y - v3.y);
        int idxD = ((j >> s2) << (s2 + 2)) + jm;
        Y[idxD]          = make_float2(t0.x + t2.x, t0.y + t2.y);
        Y[idxD + Ns]     = make_float2(t1.x + t3.y, t1.y - t3.x);
        Y[idxD + 2 * Ns] = make_float2(t0.x - t2.x, t0.y - t2.y);
        Y[idxD + 3 * Ns] = make_float2(t1.x - t3.y, t1.y + t3.x);
        float2* tmp = X; X = Y; Y = tmp;
        __syncthreads();
    }

    #pragma unroll
    for (int jj = 0; jj < 4; jj++) {
        int j = tid + jj * 256;
        float2 z  = X[j];
        float2 zn = X[(L_ - j) & (L_ - 1)];
        float2 Qf = make_float2(0.5f * (z.x + zn.x), 0.5f * (z.y - zn.y));
        float2 Kf = make_float2(0.5f * (z.y + zn.y), -0.5f * (z.x - zn.x));
        float px = Qf.x * Kf.x + Qf.y * Kf.y;
        float py = Qf.y * Kf.x - Qf.x * Kf.y;
        Y[j] = make_float2(px, -py);   // conj(P)
    }
    __syncthreads();
    { float2* tmp = X; X = Y; Y = tmp; }

    #pragma unroll
    for (int stage = 0; stage < 5; stage++) {
        int s2 = 2 * stage;
        int Ns = 1 << s2;
        int j = tid;
        float2 v0 = X[j];
        float2 v1 = X[j + 256];
        float2 v2 = X[j + 512];
        float2 v3 = X[j + 768];
        int jm = j & (Ns - 1);
        float ang = -6.28318530717958647692f * (float)jm / (float)(4 * Ns);
        float sn, cs;
        __sincosf(ang, &sn, &cs);
        float2 w1 = make_float2(cs, sn);
        float2 w2 = cmulf(w1, w1);
        float2 w3 = cmulf(w2, w1);
        v1 = cmulf(v1, w1);
        v2 = cmulf(v2, w2);
        v3 = cmulf(v3, w3);
        float2 t0 = make_float2(v0.x + v2.x, v0.y + v2.y);
        float2 t1 = make_float2(v0.x - v2.x, v0.y - v2.y);
        float2 t2 = make_float2(v1.x + v3.x, v1.y + v3.y);
        float2 t3 = make_float2(v1.x - v3.x, v1.y - v3.y);
        int idxD = ((j >> s2) << (s2 + 2)) + jm;
        Y[idxD]          = make_float2(t0.x + t2.x, t0.y + t2.y);
        Y[idxD + Ns]     = make_float2(t1.x + t3.y, t1.y - t3.x);
        Y[idxD + 2 * Ns] = make_float2(t0.x - t2.x, t0.y - t2.y);
        Y[idxD + 3 * Ns] = make_float2(t1.x - t3.y, t1.y + t3.x);
        float2* tmp = X; X = Y; Y = tmp;
        __syncthreads();
    }

    float* amp = g_amp2_t + bh * L_;
    #pragma unroll
    for (int jj = 0; jj < 4; jj++) {
        int t = tid + jj * 256;
        float ac = X[t].x * (1.0f / (float)L_);
        atomicAdd(amp + t, ac * ac);
    }
}

// Kernel 2: top-35 per (b,h). blockIdx.x = bh + 16*which.
// which=0: consume g_amp2_t then ZERO it (invariant for next replay).
// which=1: consume g_amp2_tf; also zero this bh's g_usel slice before usel accumulates.
__global__ void __launch_bounds__(256) topk_kernel() {
    int bh    = blockIdx.x & 15;
    int which = blockIdx.x >> 4;
    int tid = threadIdx.x;
    int lane = tid & 31, wrp = tid >> 5;

    float v[4];
    if (which == 0) {
        #pragma unroll
        for (int jj = 0; jj < 4; jj++)
            v[jj] = g_amp2_t[bh * L_ + tid + jj * 256];
        #pragma unroll
        for (int jj = 0; jj < 4; jj++)
            g_amp2_t[bh * L_ + tid + jj * 256] = 0.f;    // reset for next replay
    } else {
        #pragma unroll
        for (int jj = 0; jj < 4; jj++)
            v[jj] = g_amp2_tf[bh * L_ + tid + jj * 256];
        float* us = g_usel + (size_t)bh * 71 * E_;
        for (int idx = tid; idx < 71 * E_; idx += 256) us[idx] = 0.f;
    }

    __shared__ float sv[8];
    __shared__ int   si[8];

    for (int iter = 0; iter < NT_; iter++) {
        float best = v[0];
        int   bi   = tid;
        #pragma unroll
        for (int jj = 1; jj < 4; jj++) {
            if (v[jj] > best) { best = v[jj]; bi = tid + jj * 256; }
        }
        #pragma unroll
        for (int off = 16; off > 0; off >>= 1) {
            float ov = __shfl_down_sync(0xffffffffu, best, off);
            int   oi = __shfl_down_sync(0xffffffffu, bi,   off);
            if (ov > best || (ov == best && oi < bi)) { best = ov; bi = oi; }
        }
        if (lane == 0) { sv[wrp] = best; si[wrp] = bi; }
        __syncthreads();
        float wv = sv[0]; int wi = si[0];
        #pragma unroll
        for (int w = 1; w < 8; w++) {
            if (sv[w] > wv || (sv[w] == wv && si[w] < wi)) { wv = sv[w]; wi = si[w]; }
        }
        if (tid == 0) g_selidx[bh * NS_ + which * NT_ + iter] = wi;
        if ((wi & 255) == tid) v[wi >> 8] = -1.0f;
        __syncthreads();
    }
}

// Kernel 3 (R10-proven, 17.6us): usel[bh][i][d] += sum_m W[m,c_i]*V[b,m,h,d];
// row 70 uses bias. m-chunk = 32 rows, grid (32, 16), 512 threads.
__global__ void __launch_bounds__(512) usel_kernel(const float* __restrict__ W,
                                                   const float* __restrict__ bias,
                                                   const float* __restrict__ V) {
    int bh = blockIdx.y, b = bh >> 3, h = bh & 7;
    int m0 = blockIdx.x * 32;
    __shared__ float ws[71][32];
    __shared__ float vs[32][64];
    __shared__ int   cs_[NS_];
    int tid = threadIdx.x;

    if (tid < NS_) {
        cs_[tid] = g_selidx[bh * NS_ + tid] + ((tid >= NT_) ? L_ : 0);
    }
    {
        const float4* vsrc = (const float4*)(V + (((size_t)(b * L_ + m0) * H_) + h) * E_);
        int mm = tid >> 4, c4 = tid & 15;
        ((float4*)vs)[tid] = vsrc[(size_t)mm * 128 + c4];
    }
    __syncthreads();

    for (int idx = tid; idx < 71 * 32; idx += 512) {
        int i = idx >> 5, mm = idx & 31;
        float v;
        if (i < NS_) {
            v = __ldg(&W[(size_t)(m0 + mm) * (2 * L_) + cs_[i]]);
        } else {
            v = bias[m0 + mm];
        }
        ws[i][mm] = v;
    }
    __syncthreads();

    int d = tid & 63, ig = tid >> 6;   // 8 i-groups
    float acc[9];
    #pragma unroll
    for (int kk2 = 0; kk2 < 9; kk2++) acc[kk2] = 0.f;

    #pragma unroll 4
    for (int mm = 0; mm < 32; mm++) {
        float v = vs[mm][d];
        #pragma unroll
        for (int kk2 = 0; kk2 < 9; kk2++) {
            int i = ig + kk2 * 8;
            if (i < 71) acc[kk2] += ws[i][mm] * v;
        }
    }
    #pragma unroll
    for (int kk2 = 0; kk2 < 9; kk2++) {
        int i = ig + kk2 * 8;
        if (i < 71) atomicAdd(&g_usel[(size_t)(bh * 71 + i) * E_ + d], acc[kk2]);
    }
}

// Kernel 4: fused scores + softmax + combine. One block = 16 l of one (b,h),
// 128 threads, grid (64, 16).
// Phase 1: scores via packed fma.rn.f32x2 (halved FFMA issue).
// Phase 1.5: reload buf with g_usel (coalesced).
// Phase 2a: per-lt max/exp/sum computed ONCE (8 segs x 16 lt) - 16x fewer MUFU.
//           probabilities stored in-place in s[][].
// Phase 2b: combine with packed FMA; p read via LDS broadcast.
__global__ void __launch_bounds__(128) fused_kernel(const float* __restrict__ tfq,
                                                    const float* __restrict__ q,
                                                    const float* __restrict__ kk,
                                                    float* __restrict__ out) {
    int bh = blockIdx.y, b = bh >> 3, h = bh & 7;
    int tid = threadIdx.x;
    int lane16 = tid & 15;
    int g = tid >> 4;               // 8 groups of 16

    __shared__ float buf[71 * E_];      // qsel (phase 1) then usel+bias (phase 2)
    __shared__ float s[NS_][16];        // scores, then probabilities
    __shared__ float red[8][16];        // cross-seg reduction scratch
    __shared__ float mxs[16];           // per-lt max
    __shared__ float invs[16];          // per-lt 1/sum

    for (int idx = tid; idx < NS_ * E_; idx += 128) {
        int i = idx >> 6, e = idx & 63;
        int src = g_selidx[bh * NS_ + i];
        const float* sp = (i < NT_) ? q : tfq;
        buf[idx] = sp[(((size_t)(b * L_ + src) * H_) + h) * E_ + e];
    }
    __syncthreads();

    // ---- phase 1: scores (packed f32x2) ----
    {
        int half = g >> 2;              // 0: vs keys, 1: vs tf_queries
        int iseg = g & 3;
        int i0 = iseg * 9;
        int cnt = (i0 + 9 < NT_) ? 9 : (NT_ - i0);   // 9,9,9,8
        int l = blockIdx.x * 16 + lane16;

        const ulonglong2* row = (const ulonglong2*)(((half == 0) ? kk : tfq)
                            + (((size_t)(b * L_ + l) * H_) + h) * E_);
        unsigned long long pa[9];
        #pragma unroll
        for (int ii = 0; ii < 9; ii++) pa[ii] = 0ull;

        #pragma unroll
        for (int jh = 0; jh < 2; jh++) {
            ulonglong2 r2[8];
            #pragma unroll
            for (int j = 0; j < 8; j++) r2[j] = row[jh * 8 + j];

            for (int ii = 0; ii < cnt; ii++) {
                const ulonglong2* qr2 = (const ulonglong2*)&buf[(half * NT_ + i0 + ii) * E_ + jh * 32];
                unsigned long long p0 = 0ull, p1 = 0ull;
                #pragma unroll
                for (int j = 0; j < 8; j++) {
                    ulonglong2 qv = qr2[j];
                    FMA2(p0, qv.x, r2[j].x, p0);
                    FMA2(p1, qv.y, r2[j].y, p1);
                }
                ADD2(p0, p0, p1);
                ADD2(pa[ii], pa[ii], p0);
            }
        }
        for (int ii = 0; ii < cnt; ii++) {
            float lo, hi;
            UNPACK2(lo, hi, pa[ii]);
            s[half * NT_ + i0 + ii][lane16] = (lo + hi) * SCALE_;
        }
    }
    __syncthreads();   // all phase-1 reads of buf complete; s ready

    // ---- phase 1.5: stage usel (+bias row) into buf, coalesced ----
    {
        const float4* us4 = (const float4*)(g_usel + (size_t)bh * 71 * E_);
        float4* b4 = (float4*)buf;
        for (int idx = tid; idx < 71 * (E_ / 4); idx += 128)
            b4[idx] = us4[idx];
    }

    // ---- phase 2a: per-lt max / exp / sum (deduplicated MUFU) ----
    {
        int lt = tid & 15;
        int seg = tid >> 4;             // 8 segments over i
        int i0 = seg * 9;
        int cnt = (i0 + 9 < NS_) ? 9 : (NS_ - i0);   // 9*7 + 7

        float pm = -1e30f;
        for (int ii = 0; ii < cnt; ii++) pm = fmaxf(pm, s[i0 + ii][lt]);
        red[seg][lt] = pm;
        __syncthreads();

        if (tid < 16) {
            float m = red[0][tid];
            #pragma unroll
            for (int w = 1; w < 8; w++) m = fmaxf(m, red[w][tid]);
            mxs[tid] = m;
        }
        __syncthreads();

        float mx = mxs[lt];
        float ps = 0.f;
        for (int ii = 0; ii < cnt; ii++) {
            float p = __expf(s[i0 + ii][lt] - mx);
            s[i0 + ii][lt] = p;         // overwrite score with probability
            ps += p;
        }
        red[seg][lt] = ps;
        __syncthreads();

        if (tid < 16) {
            float sum = red[0][tid];
            #pragma unroll
            for (int w = 1; w < 8; w++) sum += red[w][tid];
            invs[tid] = 1.f / sum;
        }
        __syncthreads();
    }

    // ---- phase 2b: combine (packed FMA; each group: 2 l in one pass) ----
    {
        int lt0 = g * 2, lt1 = lt0 + 1;
        float inv0 = invs[lt0], inv1 = invs[lt1];
        ulonglong2 bb = ((const ulonglong2*)&buf[NS_ * E_])[lane16];

        unsigned long long a0x = 0ull, a0y = 0ull, a1x = 0ull, a1y = 0ull;

        for (int i = 0; i < NS_; i++) {
            float p0 = s[i][lt0];
            float p1 = s[i][lt1];
            unsigned long long pp0, pp1;
            PACK2(pp0, p0, p0);
            PACK2(pp1, p1, p1);
            ulonglong2 u = ((const ulonglong2*)&buf[i * E_])[lane16];
            FMA2(a0x, pp0, u.x, a0x);
            FMA2(a0y, pp0, u.y, a0y);
            FMA2(a1x, pp1, u.x, a1x);
            FMA2(a1y, pp1, u.y, a1y);
        }

        float bx0, bx1, by0, by1;
        UNPACK2(bx0, bx1, bb.x);
        UNPACK2(by0, by1, bb.y);

        float v0, v1, v2, v3;
        int l0 = blockIdx.x * 16 + lt0;
        int l1 = blockIdx.x * 16 + lt1;

        UNPACK2(v0, v1, a0x); UNPACK2(v2, v3, a0y);
        float4* op0 = (float4*)(out + (((size_t)(b * L_ + l0) * H_) + h) * E_) + lane16;
        *op0 = make_float4(v0 * inv0 + bx0, v1 * inv0 + bx1,
                           v2 * inv0 + by0, v3 * inv0 + by1);

        UNPACK2(v0, v1, a1x); UNPACK2(v2, v3, a1y);
        float4* op1 = (float4*)(out + (((size_t)(b * L_ + l1) * H_) + h) * E_) + lane16;
        *op1 = make_float4(v0 * inv1 + bx0, v1 * inv1 + bx1,
                           v2 * inv1 + by0, v3 * inv1 + by1);
    }
}

extern "C" void kernel_launch(void* const* d_in, const int* in_sizes, int n_in,
                              void* d_out, int out_size) {
    const float* tfq  = (const float*)d_in[0];
    const float* q    = (const float*)d_in[1];
    const float* k    = (const float*)d_in[2];
    const float* v    = (const float*)d_in[3];
    // d_in[4] = mask (unused)
    const float* W    = (const float*)d_in[5];
    const float* bias = (const float*)d_in[6];
    float* out = (float*)d_out;

    corr_tf_kernel<<<1040, 256>>>(q, k, tfq);
    topk_kernel<<<32, 256>>>();
    usel_kernel<<<dim3(32, BH_), 512>>>(W, bias, v);
    fused_kernel<<<dim3(64, BH_), 128>>>(tfq, q, k, out);
}

// round 16
// speedup vs baseline: 1.1303x; 1.1303x over previous
#include <cuda_runtime.h>
#include <math.h>

// Problem constants: B=2, L=1024, H=8, E=64, n_top=35 (5*ceil(ln 1024))
#define B_  2
#define L_  1024
#define H_  8
#define E_  64
#define BH_ 16
#define NT_ 35      // top-k per half
#define NS_ 70      // total selected columns
#define SCALE_ 0.125f

// -------- static scratch (no allocations allowed) --------
// Invariant: g_amp2_t and g_usel are ZERO at kernel_launch entry (zero-init at
// module load; topk_kernel re-establishes the invariant every run).
__device__ float g_amp2_t[BH_ * L_];            // corr amplitudes^2 (atomic accum)
__device__ float g_amp2_tf[BH_ * L_];           // tf-query norms^2 (overwritten)
__device__ int   g_selidx[BH_ * NS_];           // [0..34]=idx_t, [35..69]=idx_tf
__device__ float g_usel[BH_ * 71 * E_];         // row 70 = bias row bv

__device__ __forceinline__ float2 cmulf(float2 a, float2 b) {
    return make_float2(a.x * b.x - a.y * b.y, a.x * b.y + a.y * b.x);
}

// Kernel 1: blocks [0,1024): FFT circular correlation per channel (b,h,e),
// atomic-accumulating ac^2 into g_amp2_t. blocks [1024,1040): tf-query row
// norms^2 per (b,h), direct store into g_amp2_tf.
__global__ void __launch_bounds__(256) corr_tf_kernel(const float* __restrict__ q,
                                                      const float* __restrict__ k,
                                                      const float* __restrict__ tfq) {
    __shared__ float2 bufA[L_];
    __shared__ float2 bufB[L_];
    int tid = threadIdx.x;

    if (blockIdx.x >= 1024) {
        // ---- tf-norm role ----
        int bh = blockIdx.x - 1024;
        int b = bh >> 3, h = bh & 7;
        #pragma unroll
        for (int jj = 0; jj < 4; jj++) {
            int l = tid + jj * 256;
            const float4* p = (const float4*)(tfq + (((size_t)(b * L_ + l) * H_ + h) * E_));
            float s = 0.f;
            #pragma unroll
            for (int j = 0; j < 16; j++) {
                float4 x = p[j];
                s += x.x * x.x + x.y * x.y + x.z * x.z + x.w * x.w;
            }
            g_amp2_tf[bh * L_ + l] = s;
        }
        return;
    }

    // ---- corr role ----
    int ch = blockIdx.x;            // b*512 + h*64 + e
    int e  = ch & 63;
    int bh = ch >> 6;
    int h  = bh & 7;
    int b  = bh >> 3;

    size_t base = (size_t)b * (L_ * H_ * E_) + (size_t)h * E_ + e;
    #pragma unroll
    for (int jj = 0; jj < 4; jj++) {
        int l = tid + jj * 256;
        bufA[l] = make_float2(q[base + (size_t)l * (H_ * E_)],
                              k[base + (size_t)l * (H_ * E_)]);
    }
    __syncthreads();

    float2* X = bufA;
    float2* Y = bufB;

    #pragma unroll
    for (int stage = 0; stage < 5; stage++) {
        int s2 = 2 * stage;
        int Ns = 1 << s2;
        int j = tid;
        float2 v0 = X[j];
        float2 v1 = X[j + 256];
        float2 v2 = X[j + 512];
        float2 v3 = X[j + 768];
        int jm = j & (Ns - 1);
        float ang = -6.28318530717958647692f * (float)jm / (float)(4 * Ns);
        float sn, cs;
        __sincosf(ang, &sn, &cs);
        float2 w1 = make_float2(cs, sn);
        float2 w2 = cmulf(w1, w1);
        float2 w3 = cmulf(w2, w1);
        v1 = cmulf(v1, w1);
        v2 = cmulf(v2, w2);
        v3 = cmulf(v3, w3);
        float2 t0 = make_float2(v0.x + v2.x, v0.y + v2.y);
        float2 t1 = make_float2(v0.x - v2.x, v0.y - v2.y);
        float2 t2 = make_float2(v1.x + v3.x, v1.y + v3.y);
        float2 t3 = make_float2(v1.x - v3.x, v1.y - v3.y);
        int idxD = ((j >> s2) << (s2 + 2)) + jm;
        Y[idxD]          = make_float2(t0.x + t2.x, t0.y + t2.y);
        Y[idxD + Ns]     = make_float2(t1.x + t3.y, t1.y - t3.x);
        Y[idxD + 2 * Ns] = make_float2(t0.x - t2.x, t0.y - t2.y);
        Y[idxD + 3 * Ns] = make_float2(t1.x - t3.y, t1.y + t3.x);
        float2* tmp = X; X = Y; Y = tmp;
        __syncthreads();
    }

    #pragma unroll
    for (int jj = 0; jj < 4; jj++) {
        int j = tid + jj * 256;
        float2 z  = X[j];
        float2 zn = X[(L_ - j) & (L_ - 1)];
        float2 Qf = make_float2(0.5f * (z.x + zn.x), 0.5f * (z.y - zn.y));
        float2 Kf = make_float2(0.5f * (z.y + zn.y), -0.5f * (z.x - zn.x));
        float px = Qf.x * Kf.x + Qf.y * Kf.y;
        float py = Qf.y * Kf.x - Qf.x * Kf.y;
        Y[j] = make_float2(px, -py);   // conj(P)
    }
    __syncthreads();
    { float2* tmp = X; X = Y; Y = tmp; }

    #pragma unroll
    for (int stage = 0; stage < 5; stage++) {
        int s2 = 2 * stage;
        int Ns = 1 << s2;
        int j = tid;
        float2 v0 = X[j];
        float2 v1 = X[j + 256];
        float2 v2 = X[j + 512];
        float2 v3 = X[j + 768];
        int jm = j & (Ns - 1);
        float ang = -6.28318530717958647692f * (float)jm / (float)(4 * Ns);
        float sn, cs;
        __sincosf(ang, &sn, &cs);
        float2 w1 = make_float2(cs, sn);
        float2 w2 = cmulf(w1, w1);
        float2 w3 = cmulf(w2, w1);
        v1 = cmulf(v1, w1);
        v2 = cmulf(v2, w2);
        v3 = cmulf(v3, w3);
        float2 t0 = make_float2(v0.x + v2.x, v0.y + v2.y);
        float2 t1 = make_float2(v0.x - v2.x, v0.y - v2.y);
        float2 t2 = make_float2(v1.x + v3.x, v1.y + v3.y);
        float2 t3 = make_float2(v1.x - v3.x, v1.y - v3.y);
        int idxD = ((j >> s2) << (s2 + 2)) + jm;
        Y[idxD]          = make_float2(t0.x + t2.x, t0.y + t2.y);
        Y[idxD + Ns]     = make_float2(t1.x + t3.y, t1.y - t3.x);
        Y[idxD + 2 * Ns] = make_float2(t0.x - t2.x, t0.y - t2.y);
        Y[idxD + 3 * Ns] = make_float2(t1.x - t3.y, t1.y + t3.x);
        float2* tmp = X; X = Y; Y = tmp;
        __syncthreads();
    }

    float* amp = g_amp2_t + bh * L_;
    #pragma unroll
    for (int jj = 0; jj < 4; jj++) {
        int t = tid + jj * 256;
        float ac = X[t].x * (1.0f / (float)L_);
        atomicAdd(amp + t, ac * ac);
    }
}

// Kernel 2: top-35 per (b,h). blockIdx.x = bh + 16*which.
// which=0: consume g_amp2_t then ZERO it (invariant for next replay).
// which=1: consume g_amp2_tf; also zero this bh's g_usel slice before usel accumulates.
__global__ void __launch_bounds__(256) topk_kernel() {
    int bh    = blockIdx.x & 15;
    int which = blockIdx.x >> 4;
    int tid = threadIdx.x;
    int lane = tid & 31, wrp = tid >> 5;

    float v[4];
    if (which == 0) {
        #pragma unroll
        for (int jj = 0; jj < 4; jj++)
            v[jj] = g_amp2_t[bh * L_ + tid + jj * 256];
        #pragma unroll
        for (int jj = 0; jj < 4; jj++)
            g_amp2_t[bh * L_ + tid + jj * 256] = 0.f;    // reset for next replay
    } else {
        #pragma unroll
        for (int jj = 0; jj < 4; jj++)
            v[jj] = g_amp2_tf[bh * L_ + tid + jj * 256];
        float* us = g_usel + (size_t)bh * 71 * E_;
        for (int idx = tid; idx < 71 * E_; idx += 256) us[idx] = 0.f;
    }

    __shared__ float sv[8];
    __shared__ int   si[8];

    for (int iter = 0; iter < NT_; iter++) {
        float best = v[0];
        int   bi   = tid;
        #pragma unroll
        for (int jj = 1; jj < 4; jj++) {
            if (v[jj] > best) { best = v[jj]; bi = tid + jj * 256; }
        }
        #pragma unroll
        for (int off = 16; off > 0; off >>= 1) {
            float ov = __shfl_down_sync(0xffffffffu, best, off);
            int   oi = __shfl_down_sync(0xffffffffu, bi,   off);
            if (ov > best || (ov == best && oi < bi)) { best = ov; bi = oi; }
        }
        if (lane == 0) { sv[wrp] = best; si[wrp] = bi; }
        __syncthreads();
        float wv = sv[0]; int wi = si[0];
        #pragma unroll
        for (int w = 1; w < 8; w++) {
            if (sv[w] > wv || (sv[w] == wv && si[w] < wi)) { wv = sv[w]; wi = si[w]; }
        }
        if (tid == 0) g_selidx[bh * NS_ + which * NT_ + iter] = wi;
        if ((wi & 255) == tid) v[wi >> 8] = -1.0f;
        __syncthreads();
    }
}

// Kernel 3 (R10-proven, 17.6us): usel[bh][i][d] += sum_m W[m,c_i]*V[b,m,h,d];
// row 70 uses bias. m-chunk = 32 rows, grid (32, 16), 512 threads.
__global__ void __launch_bounds__(512) usel_kernel(const float* __restrict__ W,
                                                   const float* __restrict__ bias,
                                                   const float* __restrict__ V) {
    int bh = blockIdx.y, b = bh >> 3, h = bh & 7;
    int m0 = blockIdx.x * 32;
    __shared__ float ws[71][32];
    __shared__ float vs[32][64];
    __shared__ int   cs_[NS_];
    int tid = threadIdx.x;

    if (tid < NS_) {
        cs_[tid] = g_selidx[bh * NS_ + tid] + ((tid >= NT_) ? L_ : 0);
    }
    {
        const float4* vsrc = (const float4*)(V + (((size_t)(b * L_ + m0) * H_) + h) * E_);
        int mm = tid >> 4, c4 = tid & 15;
        ((float4*)vs)[tid] = vsrc[(size_t)mm * 128 + c4];
    }
    __syncthreads();

    for (int idx = tid; idx < 71 * 32; idx += 512) {
        int i = idx >> 5, mm = idx & 31;
        float v;
        if (i < NS_) {
            v = __ldg(&W[(size_t)(m0 + mm) * (2 * L_) + cs_[i]]);
        } else {
            v = bias[m0 + mm];
        }
        ws[i][mm] = v;
    }
    __syncthreads();

    int d = tid & 63, ig = tid >> 6;   // 8 i-groups
    float acc[9];
    #pragma unroll
    for (int kk2 = 0; kk2 < 9; kk2++) acc[kk2] = 0.f;

    #pragma unroll 4
    for (int mm = 0; mm < 32; mm++) {
        float v = vs[mm][d];
        #pragma unroll
        for (int kk2 = 0; kk2 < 9; kk2++) {
            int i = ig + kk2 * 8;
            if (i < 71) acc[kk2] += ws[i][mm] * v;
        }
    }
    #pragma unroll
    for (int kk2 = 0; kk2 < 9; kk2++) {
        int i = ig + kk2 * 8;
        if (i < 71) atomicAdd(&g_usel[(size_t)(bh * 71 + i) * E_ + d], acc[kk2]);
    }
}

// Kernel 4: fused scores + softmax + combine. One block = 16 l of one (b,h),
// 128 threads, grid (64, 16). Phase 1 = R13-proven float4 scores.
// Phase 1.5 = R13-proven buf reuse for usel.
// Phase 2a (NEW vs R13): per-lt max/exp/sum computed once by 8 segs x 16 lt
//   (16x fewer MUFU exp); probabilities overwrite s[][] in place.
// Phase 2b = R13's combine, with p from s (LDS broadcast) and inv from invs[].
__global__ void __launch_bounds__(128) fused_kernel(const float* __restrict__ tfq,
                                                    const float* __restrict__ q,
                                                    const float* __restrict__ kk,
                                                    float* __restrict__ out) {
    int bh = blockIdx.y, b = bh >> 3, h = bh & 7;
    int tid = threadIdx.x;
    int lane16 = tid & 15;
    int g = tid >> 4;               // 8 groups of 16

    __shared__ float buf[71 * E_];      // qsel (phase 1) then usel+bias (phase 2)
    __shared__ float s[NS_][16];        // scores, then probabilities
    __shared__ float red[8][16];        // cross-seg reduction scratch
    __shared__ float mxs[16];           // per-lt max
    __shared__ float invs[16];          // per-lt 1/sum

    for (int idx = tid; idx < NS_ * E_; idx += 128) {
        int i = idx >> 6, e = idx & 63;
        int src = g_selidx[bh * NS_ + i];
        const float* sp = (i < NT_) ? q : tfq;
        buf[idx] = sp[(((size_t)(b * L_ + src) * H_) + h) * E_ + e];
    }
    __syncthreads();

    // ---- phase 1: scores (R13 float4 version) ----
    {
        int half = g >> 2;              // 0: vs keys, 1: vs tf_queries
        int iseg = g & 3;
        int i0 = iseg * 9;
        int cnt = (i0 + 9 < NT_) ? 9 : (NT_ - i0);   // 9,9,9,8
        int l = blockIdx.x * 16 + lane16;

        const float4* row = (const float4*)(((half == 0) ? kk : tfq)
                            + (((size_t)(b * L_ + l) * H_) + h) * E_);
        float part[9];
        #pragma unroll
        for (int ii = 0; ii < 9; ii++) part[ii] = 0.f;

        #pragma unroll
        for (int jh = 0; jh < 2; jh++) {
            float4 r[8];
            #pragma unroll
            for (int j = 0; j < 8; j++) r[j] = row[jh * 8 + j];

            for (int ii = 0; ii < cnt; ii++) {
                const float4* qr = (const float4*)&buf[(half * NT_ + i0 + ii) * E_ + jh * 32];
                float s0 = 0.f, s1 = 0.f;
                #pragma unroll
                for (int j = 0; j < 4; j++) {
                    float4 qa = qr[j];
                    float4 qb = qr[j + 4];
                    s0 += qa.x * r[j].x + qa.y * r[j].y + qa.z * r[j].z + qa.w * r[j].w;
                    s1 += qb.x * r[j + 4].x + qb.y * r[j + 4].y + qb.z * r[j + 4].z + qb.w * r[j + 4].w;
                }
                part[ii] += s0 + s1;
            }
        }
        for (int ii = 0; ii < cnt; ii++)
            s[half * NT_ + i0 + ii][lane16] = part[ii] * SCALE_;
    }
    __syncthreads();   // all phase-1 reads of buf complete; s ready

    // ---- phase 1.5: stage usel (+bias row) into buf, coalesced ----
    {
        const float4* us4 = (const float4*)(g_usel + (size_t)bh * 71 * E_);
        float4* b4 = (float4*)buf;
        for (int idx = tid; idx < 71 * (E_ / 4); idx += 128)
            b4[idx] = us4[idx];
    }

    // ---- phase 2a: per-lt max / exp / sum (deduplicated MUFU) ----
    {
        int lt = tid & 15;
        int seg = tid >> 4;             // 8 segments over i
        int i0 = seg * 9;
        int cnt = (i0 + 9 < NS_) ? 9 : (NS_ - i0);   // segs 0..6: 9, seg 7: 7

        float pm = -1e30f;
        for (int ii = 0; ii < cnt; ii++) pm = fmaxf(pm, s[i0 + ii][lt]);
        red[seg][lt] = pm;
        __syncthreads();                // also orders phase-1.5 buf writes

        if (tid < 16) {
            float m = red[0][tid];
            #pragma unroll
            for (int w = 1; w < 8; w++) m = fmaxf(m, red[w][tid]);
            mxs[tid] = m;
        }
        __syncthreads();

        float mx = mxs[lt];
        float ps = 0.f;
        for (int ii = 0; ii < cnt; ii++) {
            float p = __expf(s[i0 + ii][lt] - mx);
            s[i0 + ii][lt] = p;         // overwrite score with probability
            ps += p;
        }
        red[seg][lt] = ps;
        __syncthreads();

        if (tid < 16) {
            float sum = red[0][tid];
            #pragma unroll
            for (int w = 1; w < 8; w++) sum += red[w][tid];
            invs[tid] = 1.f / sum;
        }
        __syncthreads();
    }

    // ---- phase 2b: combine (R13 float4 math; each group: 2 l in one pass) ----
    {
        int lt0 = g * 2, lt1 = lt0 + 1;
        float inv0 = invs[lt0], inv1 = invs[lt1];
        float4 bb = ((const float4*)&buf[NS_ * E_])[lane16];

        float4 acc0 = make_float4(0.f, 0.f, 0.f, 0.f);
        float4 acc1 = make_float4(0.f, 0.f, 0.f, 0.f);

        for (int i = 0; i < NS_; i++) {
            float p0 = s[i][lt0];
            float p1 = s[i][lt1];
            float4 u = ((const float4*)&buf[i * E_])[lane16];
            acc0.x += p0 * u.x; acc0.y += p0 * u.y;
            acc0.z += p0 * u.z; acc0.w += p0 * u.w;
            acc1.x += p1 * u.x; acc1.y += p1 * u.y;
            acc1.z += p1 * u.z; acc1.w += p1 * u.w;
        }
        int l0 = blockIdx.x * 16 + lt0;
        int l1 = blockIdx.x * 16 + lt1;
        float4* op0 = (float4*)(out + (((size_t)(b * L_ + l0) * H_) + h) * E_) + lane16;
        float4* op1 = (float4*)(out + (((size_t)(b * L_ + l1) * H_) + h) * E_) + lane16;
        *op0 = make_float4(acc0.x * inv0 + bb.x, acc0.y * inv0 + bb.y,
                           acc0.z * inv0 + bb.z, acc0.w * inv0 + bb.w);
        *op1 = make_float4(acc1.x * inv1 + bb.x, acc1.y * inv1 + bb.y,
                           acc1.z * inv1 + bb.z, acc1.w * inv1 + bb.w);
    }
}

extern "C" void kernel_launch(void* const* d_in, const int* in_sizes, int n_in,
                              void* d_out, int out_size) {
    const float* tfq  = (const float*)d_in[0];
    const float* q    = (const float*)d_in[1];
    const float* k    = (const float*)d_in[2];
    const float* v    = (const float*)d_in[3];
    // d_in[4] = mask (unused)
    const float* W    = (const float*)d_in[5];
    const float* bias = (const float*)d_in[6];
    float* out = (float*)d_out;

    corr_tf_kernel<<<1040, 256>>>(q, k, tfq);
    topk_kernel<<<32, 256>>>();
    usel_kernel<<<dim3(32, BH_), 512>>>(W, bias, v);
    fused_kernel<<<dim3(64, BH_), 128>>>(tfq, q, k, out);
}